// round 2
// baseline (speedup 1.0000x reference)
#include <cuda_runtime.h>
#include <math.h>

#define BATCH 256
#define SIGLEN 2048
#define L1P 1022
#define L2P 339
#define L3P 168
#define C1 128
#define C2 64
#define C3 64
#define FCIN 10752
#define EPS_BN 1e-5f

typedef unsigned long long ull;

// ---- scratch ----
__device__ float g_h1[BATCH * C1 * L1P];
__device__ float g_h2[BATCH * C2 * L2P];
__device__ float g_h3T[FCIN * BATCH];          // transposed: [feature][batch]
__device__ float g_part[96 * BATCH * 48];      // fc1 split-K partials
__device__ float g_theta[BATCH * 5];

__device__ __forceinline__ void fma2(ull& d, ull a, ull b) {
    asm("fma.rn.f32x2 %0, %1, %2, %0;" : "+l"(d) : "l"(a), "l"(b));
}
__device__ __forceinline__ ull dup2(float v) {
    ull r; asm("mov.b64 %0, {%1, %1};" : "=l"(r) : "f"(v)); return r;
}
__device__ __forceinline__ float lo32(ull v) { return __uint_as_float((unsigned)v); }
__device__ __forceinline__ float hi32(ull v) { return __uint_as_float((unsigned)(v >> 32)); }

// ============================================================
// Kernel 1: conv1 (3->128, k3) + BN + maxpool(3,2) + relu
// ============================================================
__global__ void k_conv1(const float* __restrict__ x,
                        const float* __restrict__ w,
                        const float* __restrict__ bias,
                        const float* __restrict__ bng,
                        const float* __restrict__ bnb,
                        const float* __restrict__ bnm,
                        const float* __restrict__ bnv) {
    const int b  = blockIdx.y;
    const int p0 = blockIdx.x * 64;
    const int oc = threadIdx.x;
    __shared__ float xs[3][132];

    const int t0 = 2 * p0;
    for (int idx = threadIdx.x; idx < 3 * 131; idx += 128) {
        int ch = idx / 131, j = idx % 131;
        int t = t0 + j;
        xs[ch][j] = (t < SIGLEN) ? x[(b * 3 + ch) * SIGLEN + t] : 0.f;
    }
    float wr[9];
#pragma unroll
    for (int j = 0; j < 9; ++j) wr[j] = w[oc * 9 + j];
    float scale = bng[oc] / sqrtf(bnv[oc] + EPS_BN);
    float shift = bnb[oc] + (bias[oc] - bnm[oc]) * scale;
    __syncthreads();

    for (int pl = 0; pl < 64; ++pl) {
        int p = p0 + pl;
        if (p >= L1P) break;
        float c0 = 0.f, c1 = 0.f, c2 = 0.f;
        int base = 2 * pl;
#pragma unroll
        for (int ch = 0; ch < 3; ++ch)
#pragma unroll
            for (int k = 0; k < 3; ++k) {
                float wv = wr[ch * 3 + k];
                c0 = fmaf(wv, xs[ch][base + k], c0);
                c1 = fmaf(wv, xs[ch][base + 1 + k], c1);
                c2 = fmaf(wv, xs[ch][base + 2 + k], c2);
            }
        float y0 = fmaf(c0, scale, shift);
        float y1 = fmaf(c1, scale, shift);
        float y2 = fmaf(c2, scale, shift);
        float y = fmaxf(fmaxf(y0, y1), y2);
        g_h1[(b * C1 + oc) * L1P + p] = fmaxf(y, 0.f);
    }
}

// ============================================================
// Kernel 2: conv2 (128->64, k5) + BN + maxpool(3,3) + relu  [HOT]
// f32x2 packed: thread = (ocq 0..15, gg 0..15); 4 oc via 2 pairs
// (ocq,ocq+32),(ocq+16,ocq+48); 2 pooled (6 conv) positions.
// ============================================================
__global__ void __launch_bounds__(256) k_conv2(
        const float* __restrict__ w,
        const float* __restrict__ bias,
        const float* __restrict__ bng,
        const float* __restrict__ bnb,
        const float* __restrict__ bnm,
        const float* __restrict__ bnv) {
    const int b   = blockIdx.y;
    const int p0  = blockIdx.x * 32;
    const int tid = threadIdx.x;
    const int ocq = tid & 15;
    const int gg  = tid >> 4;
    const int tbase = 3 * p0;

    __shared__ float2 xs2[16][100];       // duplicated x
    __shared__ float2 ws2[16 * 5][32];    // pair i = (w[i], w[i+32])

    ull acc0[6], acc1[6];
#pragma unroll
    for (int a = 0; a < 6; ++a) { acc0[a] = 0ull; acc1[a] = 0ull; }

    for (int chunk = 0; chunk < 8; ++chunk) {
        __syncthreads();
        const int ic0 = chunk * 16;
        for (int idx = tid; idx < 16 * 100; idx += 256) {
            int ic = idx / 100, j = idx % 100;
            int t = tbase + j;
            float v = (t < L1P) ? g_h1[(b * C1 + ic0 + ic) * L1P + t] : 0.f;
            xs2[ic][j] = make_float2(v, v);
        }
        for (int idx = tid; idx < 16 * 5 * 32; idx += 256) {
            int pr = idx & 31, r = idx >> 5;         // r = ic*5+k
            int ic = r / 5, k = r % 5;
            float wa = w[pr * 640 + (ic0 + ic) * 5 + k];
            float wb = w[(pr + 32) * 640 + (ic0 + ic) * 5 + k];
            ws2[r][pr] = make_float2(wa, wb);
        }
        __syncthreads();
#pragma unroll 4
        for (int ic = 0; ic < 16; ++ic) {
            ull xd[10];
#pragma unroll
            for (int j = 0; j < 10; ++j)
                xd[j] = *(const ull*)&xs2[ic][gg * 6 + j];
            ull w0[5], w1[5];
#pragma unroll
            for (int k = 0; k < 5; ++k) {
                w0[k] = *(const ull*)&ws2[ic * 5 + k][ocq];
                w1[k] = *(const ull*)&ws2[ic * 5 + k][ocq + 16];
            }
#pragma unroll
            for (int a = 0; a < 6; ++a)
#pragma unroll
                for (int k = 0; k < 5; ++k) {
                    fma2(acc0[a], w0[k], xd[a + k]);
                    fma2(acc1[a], w1[k], xd[a + k]);
                }
        }
    }

    const int ocs[4] = { ocq, ocq + 32, ocq + 16, ocq + 48 };
    float sc[4], sh[4];
#pragma unroll
    for (int q = 0; q < 4; ++q) {
        int oc = ocs[q];
        sc[q] = bng[oc] / sqrtf(bnv[oc] + EPS_BN);
        sh[q] = bnb[oc] + (bias[oc] - bnm[oc]) * sc[q];
    }
#pragma unroll
    for (int j = 0; j < 2; ++j) {
        int p = p0 + gg * 2 + j;
        if (p >= L2P) continue;
        float v[4][3];
#pragma unroll
        for (int m = 0; m < 3; ++m) {
            int a = 3 * j + m;
            v[0][m] = lo32(acc0[a]); v[1][m] = hi32(acc0[a]);
            v[2][m] = lo32(acc1[a]); v[3][m] = hi32(acc1[a]);
        }
#pragma unroll
        for (int q = 0; q < 4; ++q) {
            float y0 = fmaf(v[q][0], sc[q], sh[q]);
            float y1 = fmaf(v[q][1], sc[q], sh[q]);
            float y2 = fmaf(v[q][2], sc[q], sh[q]);
            g_h2[(b * C2 + ocs[q]) * L2P + p] =
                fmaxf(fmaxf(fmaxf(y0, y1), y2), 0.f);
        }
    }
}

// ============================================================
// Kernel 3: conv3 (64->64, k3) + BN + maxpool(3,2) + relu
// f32x2 packed; writes TRANSPOSED g_h3T[feature][batch]
// tile 32 pooled; thread: 5 conv accs (overlap-shared), 2 pooled.
// ============================================================
__global__ void __launch_bounds__(256) k_conv3(
        const float* __restrict__ w,
        const float* __restrict__ bias,
        const float* __restrict__ bng,
        const float* __restrict__ bnb,
        const float* __restrict__ bnm,
        const float* __restrict__ bnv) {
    const int b   = blockIdx.y;
    const int p0  = blockIdx.x * 32;
    const int tid = threadIdx.x;
    const int ocq = tid & 15;
    const int gg  = tid >> 4;
    const int tbase = 2 * p0;

    __shared__ float2 xs2[32][67];
    __shared__ float2 ws2[32 * 3][32];

    ull acc0[5], acc1[5];
#pragma unroll
    for (int a = 0; a < 5; ++a) { acc0[a] = 0ull; acc1[a] = 0ull; }

    for (int chunk = 0; chunk < 2; ++chunk) {
        __syncthreads();
        const int ic0 = chunk * 32;
        for (int idx = tid; idx < 32 * 67; idx += 256) {
            int ic = idx / 67, j = idx % 67;
            int t = tbase + j;
            float v = (t < L2P) ? g_h2[(b * C2 + ic0 + ic) * L2P + t] : 0.f;
            xs2[ic][j] = make_float2(v, v);
        }
        for (int idx = tid; idx < 32 * 3 * 32; idx += 256) {
            int pr = idx & 31, r = idx >> 5;       // r = ic*3+k
            int ic = r / 3, k = r % 3;
            float wa = w[pr * 192 + (ic0 + ic) * 3 + k];
            float wb = w[(pr + 32) * 192 + (ic0 + ic) * 3 + k];
            ws2[r][pr] = make_float2(wa, wb);
        }
        __syncthreads();
#pragma unroll 4
        for (int ic = 0; ic < 32; ++ic) {
            ull xd[7];
#pragma unroll
            for (int j = 0; j < 7; ++j)
                xd[j] = *(const ull*)&xs2[ic][gg * 4 + j];
            ull w0[3], w1[3];
#pragma unroll
            for (int k = 0; k < 3; ++k) {
                w0[k] = *(const ull*)&ws2[ic * 3 + k][ocq];
                w1[k] = *(const ull*)&ws2[ic * 3 + k][ocq + 16];
            }
#pragma unroll
            for (int a = 0; a < 5; ++a)
#pragma unroll
                for (int k = 0; k < 3; ++k) {
                    fma2(acc0[a], w0[k], xd[a + k]);
                    fma2(acc1[a], w1[k], xd[a + k]);
                }
        }
    }

    const int ocs[4] = { ocq, ocq + 32, ocq + 16, ocq + 48 };
    float sc[4], sh[4];
#pragma unroll
    for (int q = 0; q < 4; ++q) {
        int oc = ocs[q];
        sc[q] = bng[oc] / sqrtf(bnv[oc] + EPS_BN);
        sh[q] = bnb[oc] + (bias[oc] - bnm[oc]) * sc[q];
    }
#pragma unroll
    for (int j = 0; j < 2; ++j) {
        int p = p0 + gg * 2 + j;
        if (p >= L3P) continue;
        float v[4][3];
#pragma unroll
        for (int m = 0; m < 3; ++m) {
            int a = 2 * j + m;          // j=0: accs 0,1,2 ; j=1: accs 2,3,4
            v[0][m] = lo32(acc0[a]); v[1][m] = hi32(acc0[a]);
            v[2][m] = lo32(acc1[a]); v[3][m] = hi32(acc1[a]);
        }
#pragma unroll
        for (int q = 0; q < 4; ++q) {
            float y0 = fmaf(v[q][0], sc[q], sh[q]);
            float y1 = fmaf(v[q][1], sc[q], sh[q]);
            float y2 = fmaf(v[q][2], sc[q], sh[q]);
            float y = fmaxf(fmaxf(fmaxf(y0, y1), y2), 0.f);
            g_h3T[(ocs[q] * L3P + p) * BATCH + b] = y;
        }
    }
}

// ============================================================
// Kernel 4a: fc1 split-K. block = K-chunk (96 x 112); thread = batch row.
// Weights read once total; x reads coalesced via g_h3T.
// ============================================================
__global__ void __launch_bounds__(256) k_fcA(const float* __restrict__ fc1w) {
    const int chunk = blockIdx.x;
    const int r = threadIdx.x;
    __shared__ float2 ws2[112][24];    // pair (o, o+24)

    for (int idx = r; idx < 112 * 24; idx += 256) {
        int pr = idx % 24, k = idx / 24;
        int kg = chunk * 112 + k;
        ws2[k][pr] = make_float2(fc1w[pr * FCIN + kg],
                                 fc1w[(pr + 24) * FCIN + kg]);
    }
    __syncthreads();

    ull acc[24];
#pragma unroll
    for (int p = 0; p < 24; ++p) acc[p] = 0ull;

#pragma unroll 4
    for (int k = 0; k < 112; ++k) {
        float xv = g_h3T[(chunk * 112 + k) * BATCH + r];
        ull xd = dup2(xv);
#pragma unroll
        for (int p = 0; p < 24; ++p)
            fma2(acc[p], *(const ull*)&ws2[k][p], xd);
    }
    float* outp = &g_part[(chunk * BATCH + r) * 48];
#pragma unroll
    for (int p = 0; p < 24; ++p) {
        outp[p]      = lo32(acc[p]);
        outp[p + 24] = hi32(acc[p]);
    }
}

// ============================================================
// Kernel 4b: reduce partials + bias + relu, then fc2/fc3/fc4+tanh
// ============================================================
__global__ void k_fcB(const float* __restrict__ fc1b,
                      const float* __restrict__ fc2w, const float* __restrict__ fc2b,
                      const float* __restrict__ fc3w, const float* __restrict__ fc3b,
                      const float* __restrict__ fc4w, const float* __restrict__ fc4b) {
    const int r = blockIdx.x;
    const int t = threadIdx.x;
    __shared__ float s1[48], s2[32], s3[16];

    if (t < 48) {
        float a = 0.f;
#pragma unroll 8
        for (int c = 0; c < 96; ++c)
            a += g_part[(c * BATCH + r) * 48 + t];
        s1[t] = fmaxf(a + fc1b[t], 0.f);
    }
    __syncthreads();
    if (t < 32) {
        float a2 = 0.f;
#pragma unroll
        for (int k = 0; k < 48; ++k) a2 = fmaf(s1[k], fc2w[t * 48 + k], a2);
        s2[t] = fmaxf(a2 + fc2b[t], 0.f);
    }
    __syncthreads();
    if (t < 16) {
        float a3 = 0.f;
#pragma unroll
        for (int k = 0; k < 32; ++k) a3 = fmaf(s2[k], fc3w[t * 32 + k], a3);
        s3[t] = fmaxf(a3 + fc3b[t], 0.f);
    }
    __syncthreads();
    if (t < 5) {
        float a4 = 0.f;
#pragma unroll
        for (int k = 0; k < 16; ++k) a4 = fmaf(s3[k], fc4w[t * 16 + k], a4);
        g_theta[r * 5 + t] = tanhf(a4 + fc4b[t]);
    }
}

// ============================================================
// Kernel 5: CPAB integrate + resample
// ============================================================
__global__ void k_warp(const float* __restrict__ x,
                       const float* __restrict__ basis,
                       float* __restrict__ out) {
    const int b   = blockIdx.x;
    const int tid = threadIdx.x;
    __shared__ float sa[6], sb[6];
    if (tid < 12) {
        float a = 0.f;
#pragma unroll
        for (int k = 0; k < 5; ++k)
            a = fmaf(g_theta[b * 5 + k], basis[tid * 5 + k], a);
        if (tid & 1) sb[tid >> 1] = a; else sa[tid >> 1] = a;
    }
    __syncthreads();
    float la[6], lb[6];
#pragma unroll
    for (int c = 0; c < 6; ++c) { la[c] = sa[c]; lb[c] = sb[c]; }
    const float INF = __int_as_float(0x7f800000);

    for (int r = 0; r < 8; ++r) {
        int i = tid + r * 256;
        float xv = (float)i / 2047.0f;
        float t = 1.0f;
#pragma unroll 1
        for (int it = 0; it < 7; ++it) {
            int c = (int)floorf(xv * 6.0f);
            c = c < 0 ? 0 : (c > 5 ? 5 : c);
            float a  = la[c];
            float bc = lb[c];
            float v  = fmaf(a, xv, bc);
            float xb = (v >= 0.f) ? (float)(c + 1) / 6.0f : (float)c / 6.0f;
            bool  big = fabsf(a) > 1e-8f;
            float a_s = big ? a : 1.0f;
            float boa = bc / a_s;
            float z   = xv + boa;
            float zb  = xb + boa;
            float zden  = (fabsf(z) > 1e-12f) ? z : 1e-12f;
            float ratio = zb / zden;
            float t_exp = logf(fmaxf(ratio, 1e-12f)) / a_s;
            float v_s   = (fabsf(v) > 1e-12f) ? v : 1.0f;
            float t_lin = (xb - xv) / v_s;
            float thit  = big ? t_exp : t_lin;
            bool valid = (fabsf(v) > 1e-12f) && (thit > 0.f) &&
                         ((big ? ratio : 1.0f) > 0.f);
            thit = valid ? thit : INF;
            float tau = fminf(t, thit);
            float x_new = big ? (z * expf(a * tau) - (z - xv))
                              : fmaf(bc, tau, xv);
            bool hit = (thit <= t);
            float nudge = (v >= 0.f) ? 1e-6f : -1e-6f;
            xv = hit ? (xb + nudge) : x_new;
            xv = fminf(fmaxf(xv, 0.f), 1.f);
            t = fmaxf(t - tau, 0.f);
        }
        float p = fminf(fmaxf(xv, 0.f), 1.f) * 2047.0f;
        int x0 = (int)floorf(p);
        x0 = x0 < 0 ? 0 : (x0 > 2046 ? 2046 : x0);
        float wgt = p - (float)x0;
#pragma unroll
        for (int ch = 0; ch < 3; ++ch) {
            float d0 = x[(b * 3 + ch) * SIGLEN + x0];
            float d1 = x[(b * 3 + ch) * SIGLEN + x0 + 1];
            out[(b * 3 + ch) * SIGLEN + i] = d0 * (1.0f - wgt) + d1 * wgt;
        }
    }
}

// ============================================================
extern "C" void kernel_launch(void* const* d_in, const int* in_sizes, int n_in,
                              void* d_out, int out_size) {
    const float* x     = (const float*)d_in[0];
    const float* c1w   = (const float*)d_in[1];
    const float* c1b   = (const float*)d_in[2];
    const float* bn1g  = (const float*)d_in[3];
    const float* bn1b  = (const float*)d_in[4];
    const float* bn1m  = (const float*)d_in[5];
    const float* bn1v  = (const float*)d_in[6];
    const float* c2w   = (const float*)d_in[7];
    const float* c2b   = (const float*)d_in[8];
    const float* bn2g  = (const float*)d_in[9];
    const float* bn2b  = (const float*)d_in[10];
    const float* bn2m  = (const float*)d_in[11];
    const float* bn2v  = (const float*)d_in[12];
    const float* c3w   = (const float*)d_in[13];
    const float* c3b   = (const float*)d_in[14];
    const float* bn3g  = (const float*)d_in[15];
    const float* bn3b  = (const float*)d_in[16];
    const float* bn3m  = (const float*)d_in[17];
    const float* bn3v  = (const float*)d_in[18];
    const float* fc1w  = (const float*)d_in[19];
    const float* fc1b  = (const float*)d_in[20];
    const float* fc2w  = (const float*)d_in[21];
    const float* fc2b  = (const float*)d_in[22];
    const float* fc3w  = (const float*)d_in[23];
    const float* fc3b  = (const float*)d_in[24];
    const float* fc4w  = (const float*)d_in[25];
    const float* fc4b  = (const float*)d_in[26];
    const float* basis = (const float*)d_in[27];
    float* out = (float*)d_out;

    dim3 g1(16, BATCH);  k_conv1<<<g1, 128>>>(x, c1w, c1b, bn1g, bn1b, bn1m, bn1v);
    dim3 g2(11, BATCH);  k_conv2<<<g2, 256>>>(c2w, c2b, bn2g, bn2b, bn2m, bn2v);
    dim3 g3(6,  BATCH);  k_conv3<<<g3, 256>>>(c3w, c3b, bn3g, bn3b, bn3m, bn3v);
    k_fcA<<<96, 256>>>(fc1w);
    k_fcB<<<BATCH, 64>>>(fc1b, fc2w, fc2b, fc3w, fc3b, fc4w, fc4b);
    k_warp<<<BATCH, 256>>>(x, basis, out);
}

// round 3
// speedup vs baseline: 1.1610x; 1.1610x over previous
#include <cuda_runtime.h>
#include <math.h>

#define BATCH 256
#define SIGLEN 2048
#define L1P 1022
#define L2P 339
#define L3P 168
#define C1 128
#define C2 64
#define C3 64
#define FCIN 10752
#define EPS_BN 1e-5f

typedef unsigned long long ull;

// ---- scratch ----
__device__ float g_h1[BATCH * C1 * L1P];
__device__ float g_h2[BATCH * C2 * L2P];
__device__ float g_h3T[FCIN * BATCH];          // [feature][batch]
__device__ float g_part[96 * BATCH * 48];
__device__ float g_theta[BATCH * 5];

__device__ __forceinline__ void fma2(ull& d, ull a, ull b) {
    asm("fma.rn.f32x2 %0, %1, %2, %0;" : "+l"(d) : "l"(a), "l"(b));
}
__device__ __forceinline__ ull dup2(float v) {
    ull r; asm("mov.b64 %0, {%1, %1};" : "=l"(r) : "f"(v)); return r;
}
__device__ __forceinline__ float lo32(ull v) { return __uint_as_float((unsigned)v); }
__device__ __forceinline__ float hi32(ull v) { return __uint_as_float((unsigned)(v >> 32)); }

// ============================================================
// Kernel 1: conv1 (3->128, k3) + BN + maxpool(3,2) + relu
// compute: thread = oc; output staged in smem, coalesced STG.
// ============================================================
__global__ void __launch_bounds__(128) k_conv1(
        const float* __restrict__ x,
        const float* __restrict__ w,
        const float* __restrict__ bias,
        const float* __restrict__ bng,
        const float* __restrict__ bnb,
        const float* __restrict__ bnm,
        const float* __restrict__ bnv) {
    const int b  = blockIdx.y;
    const int p0 = blockIdx.x * 64;
    const int oc = threadIdx.x;
    __shared__ float xs[3][132];
    __shared__ float outS[128][65];   // padded rows

    const int t0 = 2 * p0;
    for (int idx = threadIdx.x; idx < 3 * 131; idx += 128) {
        int ch = idx / 131, j = idx % 131;
        int t = t0 + j;
        xs[ch][j] = (t < SIGLEN) ? x[(b * 3 + ch) * SIGLEN + t] : 0.f;
    }
    float wr[9];
#pragma unroll
    for (int j = 0; j < 9; ++j) wr[j] = w[oc * 9 + j];
    float scale = bng[oc] / sqrtf(bnv[oc] + EPS_BN);
    float shift = bnb[oc] + (bias[oc] - bnm[oc]) * scale;
    __syncthreads();

#pragma unroll 4
    for (int pl = 0; pl < 64; ++pl) {
        float c0 = 0.f, c1 = 0.f, c2 = 0.f;
        int base = 2 * pl;
#pragma unroll
        for (int ch = 0; ch < 3; ++ch)
#pragma unroll
            for (int k = 0; k < 3; ++k) {
                float wv = wr[ch * 3 + k];
                c0 = fmaf(wv, xs[ch][base + k], c0);
                c1 = fmaf(wv, xs[ch][base + 1 + k], c1);
                c2 = fmaf(wv, xs[ch][base + 2 + k], c2);
            }
        float y0 = fmaf(c0, scale, shift);
        float y1 = fmaf(c1, scale, shift);
        float y2 = fmaf(c2, scale, shift);
        outS[oc][pl] = fmaxf(fmaxf(fmaxf(y0, y1), y2), 0.f);
    }
    __syncthreads();
    // coalesced write-out: 64 consecutive pos per oc row
    for (int idx = threadIdx.x; idx < 128 * 64; idx += 128) {
        int o = idx >> 6, j = idx & 63;
        int p = p0 + j;
        if (p < L1P) g_h1[(b * C1 + o) * L1P + p] = outS[o][j];
    }
}

// ============================================================
// Kernel 2: conv2 (128->64, k5) + BN + maxpool(3,3) + relu  [HOT]
// f32x2; thread = (ocq 0..15, gg 0..15); 4 oc x 2 pooled.
// NO outer unroll (register-pressure control). Staged coalesced out.
// ============================================================
__global__ void __launch_bounds__(256) k_conv2(
        const float* __restrict__ w,
        const float* __restrict__ bias,
        const float* __restrict__ bng,
        const float* __restrict__ bnb,
        const float* __restrict__ bnm,
        const float* __restrict__ bnv) {
    const int b   = blockIdx.y;
    const int p0  = blockIdx.x * 32;
    const int tid = threadIdx.x;
    const int ocq = tid & 15;
    const int gg  = tid >> 4;
    const int tbase = 3 * p0;

    __shared__ float2 xs2[16][100];
    __shared__ float2 ws2[16 * 5][32];
    __shared__ float outS[64][33];

    ull acc0[6], acc1[6];
#pragma unroll
    for (int a = 0; a < 6; ++a) { acc0[a] = 0ull; acc1[a] = 0ull; }

    for (int chunk = 0; chunk < 8; ++chunk) {
        __syncthreads();
        const int ic0 = chunk * 16;
        for (int idx = tid; idx < 16 * 100; idx += 256) {
            int ic = idx / 100, j = idx % 100;
            int t = tbase + j;
            float v = (t < L1P) ? g_h1[(b * C1 + ic0 + ic) * L1P + t] : 0.f;
            xs2[ic][j] = make_float2(v, v);
        }
        for (int idx = tid; idx < 16 * 5 * 32; idx += 256) {
            int pr = idx & 31, r = idx >> 5;
            int ic = r / 5, k = r % 5;
            float wa = w[pr * 640 + (ic0 + ic) * 5 + k];
            float wb = w[(pr + 32) * 640 + (ic0 + ic) * 5 + k];
            ws2[r][pr] = make_float2(wa, wb);
        }
        __syncthreads();
#pragma unroll 1
        for (int ic = 0; ic < 16; ++ic) {
            ull xd[10];
#pragma unroll
            for (int j = 0; j < 10; ++j)
                xd[j] = *(const ull*)&xs2[ic][gg * 6 + j];
            ull w0[5], w1[5];
#pragma unroll
            for (int k = 0; k < 5; ++k) {
                w0[k] = *(const ull*)&ws2[ic * 5 + k][ocq];
                w1[k] = *(const ull*)&ws2[ic * 5 + k][ocq + 16];
            }
#pragma unroll
            for (int a = 0; a < 6; ++a)
#pragma unroll
                for (int k = 0; k < 5; ++k) {
                    fma2(acc0[a], w0[k], xd[a + k]);
                    fma2(acc1[a], w1[k], xd[a + k]);
                }
        }
    }

    const int ocs[4] = { ocq, ocq + 32, ocq + 16, ocq + 48 };
    float sc[4], sh[4];
#pragma unroll
    for (int q = 0; q < 4; ++q) {
        int oc = ocs[q];
        sc[q] = bng[oc] / sqrtf(bnv[oc] + EPS_BN);
        sh[q] = bnb[oc] + (bias[oc] - bnm[oc]) * sc[q];
    }
#pragma unroll
    for (int j = 0; j < 2; ++j) {
        float v[4][3];
#pragma unroll
        for (int m = 0; m < 3; ++m) {
            int a = 3 * j + m;
            v[0][m] = lo32(acc0[a]); v[1][m] = hi32(acc0[a]);
            v[2][m] = lo32(acc1[a]); v[3][m] = hi32(acc1[a]);
        }
#pragma unroll
        for (int q = 0; q < 4; ++q) {
            float y0 = fmaf(v[q][0], sc[q], sh[q]);
            float y1 = fmaf(v[q][1], sc[q], sh[q]);
            float y2 = fmaf(v[q][2], sc[q], sh[q]);
            outS[ocs[q]][gg * 2 + j] = fmaxf(fmaxf(fmaxf(y0, y1), y2), 0.f);
        }
    }
    __syncthreads();
    for (int idx = tid; idx < 64 * 32; idx += 256) {
        int o = idx >> 5, j = idx & 31;
        int p = p0 + j;
        if (p < L2P) g_h2[(b * C2 + o) * L2P + p] = outS[o][j];
    }
}

// ============================================================
// Kernel 3: conv3 (64->64, k3) + BN + maxpool(3,2) + relu
// f32x2; writes transposed g_h3T[feature][batch]
// ============================================================
__global__ void __launch_bounds__(256) k_conv3(
        const float* __restrict__ w,
        const float* __restrict__ bias,
        const float* __restrict__ bng,
        const float* __restrict__ bnb,
        const float* __restrict__ bnm,
        const float* __restrict__ bnv) {
    const int b   = blockIdx.y;
    const int p0  = blockIdx.x * 32;
    const int tid = threadIdx.x;
    const int ocq = tid & 15;
    const int gg  = tid >> 4;
    const int tbase = 2 * p0;

    __shared__ float2 xs2[32][67];
    __shared__ float2 ws2[32 * 3][32];

    ull acc0[5], acc1[5];
#pragma unroll
    for (int a = 0; a < 5; ++a) { acc0[a] = 0ull; acc1[a] = 0ull; }

    for (int chunk = 0; chunk < 2; ++chunk) {
        __syncthreads();
        const int ic0 = chunk * 32;
        for (int idx = tid; idx < 32 * 67; idx += 256) {
            int ic = idx / 67, j = idx % 67;
            int t = tbase + j;
            float v = (t < L2P) ? g_h2[(b * C2 + ic0 + ic) * L2P + t] : 0.f;
            xs2[ic][j] = make_float2(v, v);
        }
        for (int idx = tid; idx < 32 * 3 * 32; idx += 256) {
            int pr = idx & 31, r = idx >> 5;
            int ic = r / 3, k = r % 3;
            float wa = w[pr * 192 + (ic0 + ic) * 3 + k];
            float wb = w[(pr + 32) * 192 + (ic0 + ic) * 3 + k];
            ws2[r][pr] = make_float2(wa, wb);
        }
        __syncthreads();
#pragma unroll 1
        for (int ic = 0; ic < 32; ++ic) {
            ull xd[7];
#pragma unroll
            for (int j = 0; j < 7; ++j)
                xd[j] = *(const ull*)&xs2[ic][gg * 4 + j];
            ull w0[3], w1[3];
#pragma unroll
            for (int k = 0; k < 3; ++k) {
                w0[k] = *(const ull*)&ws2[ic * 3 + k][ocq];
                w1[k] = *(const ull*)&ws2[ic * 3 + k][ocq + 16];
            }
#pragma unroll
            for (int a = 0; a < 5; ++a)
#pragma unroll
                for (int k = 0; k < 3; ++k) {
                    fma2(acc0[a], w0[k], xd[a + k]);
                    fma2(acc1[a], w1[k], xd[a + k]);
                }
        }
    }

    const int ocs[4] = { ocq, ocq + 32, ocq + 16, ocq + 48 };
    float sc[4], sh[4];
#pragma unroll
    for (int q = 0; q < 4; ++q) {
        int oc = ocs[q];
        sc[q] = bng[oc] / sqrtf(bnv[oc] + EPS_BN);
        sh[q] = bnb[oc] + (bias[oc] - bnm[oc]) * sc[q];
    }
#pragma unroll
    for (int j = 0; j < 2; ++j) {
        int p = p0 + gg * 2 + j;
        if (p >= L3P) continue;
        float v[4][3];
#pragma unroll
        for (int m = 0; m < 3; ++m) {
            int a = 2 * j + m;
            v[0][m] = lo32(acc0[a]); v[1][m] = hi32(acc0[a]);
            v[2][m] = lo32(acc1[a]); v[3][m] = hi32(acc1[a]);
        }
#pragma unroll
        for (int q = 0; q < 4; ++q) {
            float y0 = fmaf(v[q][0], sc[q], sh[q]);
            float y1 = fmaf(v[q][1], sc[q], sh[q]);
            float y2 = fmaf(v[q][2], sc[q], sh[q]);
            float y = fmaxf(fmaxf(fmaxf(y0, y1), y2), 0.f);
            g_h3T[(ocs[q] * L3P + p) * BATCH + b] = y;
        }
    }
}

// ============================================================
// Kernel 4a: fc1 split-K. 96 blocks x 112-wide K chunks.
// ============================================================
__global__ void __launch_bounds__(256) k_fcA(const float* __restrict__ fc1w) {
    const int chunk = blockIdx.x;
    const int r = threadIdx.x;
    __shared__ float2 ws2[112][24];

    for (int idx = r; idx < 112 * 24; idx += 256) {
        int pr = idx % 24, k = idx / 24;
        int kg = chunk * 112 + k;
        ws2[k][pr] = make_float2(fc1w[pr * FCIN + kg],
                                 fc1w[(pr + 24) * FCIN + kg]);
    }
    __syncthreads();

    ull acc[24];
#pragma unroll
    for (int p = 0; p < 24; ++p) acc[p] = 0ull;

#pragma unroll 4
    for (int k = 0; k < 112; ++k) {
        float xv = g_h3T[(chunk * 112 + k) * BATCH + r];
        ull xd = dup2(xv);
#pragma unroll
        for (int p = 0; p < 24; ++p)
            fma2(acc[p], *(const ull*)&ws2[k][p], xd);
    }
    float* outp = &g_part[(chunk * BATCH + r) * 48];
#pragma unroll
    for (int p = 0; p < 24; ++p) {
        outp[p]      = lo32(acc[p]);
        outp[p + 24] = hi32(acc[p]);
    }
}

// ============================================================
// Kernel 4b: reduce + fc2/fc3/fc4 + tanh
// ============================================================
__global__ void k_fcB(const float* __restrict__ fc1b,
                      const float* __restrict__ fc2w, const float* __restrict__ fc2b,
                      const float* __restrict__ fc3w, const float* __restrict__ fc3b,
                      const float* __restrict__ fc4w, const float* __restrict__ fc4b) {
    const int r = blockIdx.x;
    const int t = threadIdx.x;
    __shared__ float s1[48], s2[32], s3[16];

    if (t < 48) {
        float a = 0.f;
#pragma unroll 8
        for (int c = 0; c < 96; ++c)
            a += g_part[(c * BATCH + r) * 48 + t];
        s1[t] = fmaxf(a + fc1b[t], 0.f);
    }
    __syncthreads();
    if (t < 32) {
        float a2 = 0.f;
#pragma unroll
        for (int k = 0; k < 48; ++k) a2 = fmaf(s1[k], fc2w[t * 48 + k], a2);
        s2[t] = fmaxf(a2 + fc2b[t], 0.f);
    }
    __syncthreads();
    if (t < 16) {
        float a3 = 0.f;
#pragma unroll
        for (int k = 0; k < 32; ++k) a3 = fmaf(s2[k], fc3w[t * 32 + k], a3);
        s3[t] = fmaxf(a3 + fc3b[t], 0.f);
    }
    __syncthreads();
    if (t < 5) {
        float a4 = 0.f;
#pragma unroll
        for (int k = 0; k < 16; ++k) a4 = fmaf(s3[k], fc4w[t * 16 + k], a4);
        g_theta[r * 5 + t] = tanhf(a4 + fc4b[t]);
    }
}

// ============================================================
// Kernel 5: CPAB integrate + resample
// ============================================================
__global__ void k_warp(const float* __restrict__ x,
                       const float* __restrict__ basis,
                       float* __restrict__ out) {
    const int b   = blockIdx.x;
    const int tid = threadIdx.x;
    __shared__ float sa[6], sb[6];
    if (tid < 12) {
        float a = 0.f;
#pragma unroll
        for (int k = 0; k < 5; ++k)
            a = fmaf(g_theta[b * 5 + k], basis[tid * 5 + k], a);
        if (tid & 1) sb[tid >> 1] = a; else sa[tid >> 1] = a;
    }
    __syncthreads();
    float la[6], lb[6];
#pragma unroll
    for (int c = 0; c < 6; ++c) { la[c] = sa[c]; lb[c] = sb[c]; }
    const float INF = __int_as_float(0x7f800000);

    for (int r = 0; r < 8; ++r) {
        int i = tid + r * 256;
        float xv = (float)i / 2047.0f;
        float t = 1.0f;
#pragma unroll 1
        for (int it = 0; it < 7; ++it) {
            int c = (int)floorf(xv * 6.0f);
            c = c < 0 ? 0 : (c > 5 ? 5 : c);
            float a  = la[c];
            float bc = lb[c];
            float v  = fmaf(a, xv, bc);
            float xb = (v >= 0.f) ? (float)(c + 1) / 6.0f : (float)c / 6.0f;
            bool  big = fabsf(a) > 1e-8f;
            float a_s = big ? a : 1.0f;
            float boa = bc / a_s;
            float z   = xv + boa;
            float zb  = xb + boa;
            float zden  = (fabsf(z) > 1e-12f) ? z : 1e-12f;
            float ratio = zb / zden;
            float t_exp = logf(fmaxf(ratio, 1e-12f)) / a_s;
            float v_s   = (fabsf(v) > 1e-12f) ? v : 1.0f;
            float t_lin = (xb - xv) / v_s;
            float thit  = big ? t_exp : t_lin;
            bool valid = (fabsf(v) > 1e-12f) && (thit > 0.f) &&
                         ((big ? ratio : 1.0f) > 0.f);
            thit = valid ? thit : INF;
            float tau = fminf(t, thit);
            float x_new = big ? (z * expf(a * tau) - (z - xv))
                              : fmaf(bc, tau, xv);
            bool hit = (thit <= t);
            float nudge = (v >= 0.f) ? 1e-6f : -1e-6f;
            xv = hit ? (xb + nudge) : x_new;
            xv = fminf(fmaxf(xv, 0.f), 1.f);
            t = fmaxf(t - tau, 0.f);
        }
        float p = fminf(fmaxf(xv, 0.f), 1.f) * 2047.0f;
        int x0 = (int)floorf(p);
        x0 = x0 < 0 ? 0 : (x0 > 2046 ? 2046 : x0);
        float wgt = p - (float)x0;
#pragma unroll
        for (int ch = 0; ch < 3; ++ch) {
            float d0 = x[(b * 3 + ch) * SIGLEN + x0];
            float d1 = x[(b * 3 + ch) * SIGLEN + x0 + 1];
            out[(b * 3 + ch) * SIGLEN + i] = d0 * (1.0f - wgt) + d1 * wgt;
        }
    }
}

// ============================================================
extern "C" void kernel_launch(void* const* d_in, const int* in_sizes, int n_in,
                              void* d_out, int out_size) {
    const float* x     = (const float*)d_in[0];
    const float* c1w   = (const float*)d_in[1];
    const float* c1b   = (const float*)d_in[2];
    const float* bn1g  = (const float*)d_in[3];
    const float* bn1b  = (const float*)d_in[4];
    const float* bn1m  = (const float*)d_in[5];
    const float* bn1v  = (const float*)d_in[6];
    const float* c2w   = (const float*)d_in[7];
    const float* c2b   = (const float*)d_in[8];
    const float* bn2g  = (const float*)d_in[9];
    const float* bn2b  = (const float*)d_in[10];
    const float* bn2m  = (const float*)d_in[11];
    const float* bn2v  = (const float*)d_in[12];
    const float* c3w   = (const float*)d_in[13];
    const float* c3b   = (const float*)d_in[14];
    const float* bn3g  = (const float*)d_in[15];
    const float* bn3b  = (const float*)d_in[16];
    const float* bn3m  = (const float*)d_in[17];
    const float* bn3v  = (const float*)d_in[18];
    const float* fc1w  = (const float*)d_in[19];
    const float* fc1b  = (const float*)d_in[20];
    const float* fc2w  = (const float*)d_in[21];
    const float* fc2b  = (const float*)d_in[22];
    const float* fc3w  = (const float*)d_in[23];
    const float* fc3b  = (const float*)d_in[24];
    const float* fc4w  = (const float*)d_in[25];
    const float* fc4b  = (const float*)d_in[26];
    const float* basis = (const float*)d_in[27];
    float* out = (float*)d_out;

    dim3 g1(16, BATCH);  k_conv1<<<g1, 128>>>(x, c1w, c1b, bn1g, bn1b, bn1m, bn1v);
    dim3 g2(11, BATCH);  k_conv2<<<g2, 256>>>(c2w, c2b, bn2g, bn2b, bn2m, bn2v);
    dim3 g3(6,  BATCH);  k_conv3<<<g3, 256>>>(c3w, c3b, bn3g, bn3b, bn3m, bn3v);
    k_fcA<<<96, 256>>>(fc1w);
    k_fcB<<<BATCH, 64>>>(fc1b, fc2w, fc2b, fc3w, fc3b, fc4w, fc4b);
    k_warp<<<BATCH, 256>>>(x, basis, out);
}

// round 4
// speedup vs baseline: 1.2220x; 1.0525x over previous
#include <cuda_runtime.h>
#include <math.h>

#define BATCH 256
#define SIGLEN 2048
#define L1P 1022
#define L2P 339
#define L3P 168
#define C1 128
#define C2 64
#define C3 64
#define FCIN 10752
#define EPS_BN 1e-5f

typedef unsigned long long ull;

// ---- scratch ----
__device__ float g_h1T[BATCH * L1P * C1];   // [b][pos][ic]
__device__ float g_h2T[BATCH * L2P * C2];   // [b][pos][oc]
__device__ float g_h3T[FCIN * BATCH];       // [feature][batch]
__device__ float g_w2T[5 * 64 * 128];       // [k][oc][ic]
__device__ float g_w3T[3 * 64 * 64];        // [k][oc][ic]
__device__ float g_part[192 * BATCH * 48];
__device__ float g_theta[BATCH * 5];

__device__ __forceinline__ void fma2(ull& d, ull a, ull b) {
    asm("fma.rn.f32x2 %0, %1, %2, %0;" : "+l"(d) : "l"(a), "l"(b));
}
__device__ __forceinline__ ull dup2(float v) {
    ull r; asm("mov.b64 %0, {%1, %1};" : "=l"(r) : "f"(v)); return r;
}
__device__ __forceinline__ float lo32(ull v) { return __uint_as_float((unsigned)v); }
__device__ __forceinline__ float hi32(ull v) { return __uint_as_float((unsigned)(v >> 32)); }

__device__ __forceinline__ void cpa16(void* dst, const void* src) {
    unsigned d = (unsigned)__cvta_generic_to_shared(dst);
    asm volatile("cp.async.cg.shared.global [%0], [%1], 16;" :: "r"(d), "l"(src));
}
__device__ __forceinline__ void cpa8(void* dst, const void* src) {
    unsigned d = (unsigned)__cvta_generic_to_shared(dst);
    asm volatile("cp.async.ca.shared.global [%0], [%1], 8;" :: "r"(d), "l"(src));
}
#define CP_COMMIT()  asm volatile("cp.async.commit_group;" ::: "memory")
#define CP_WAIT1()   asm volatile("cp.async.wait_group 1;" ::: "memory")
#define CP_WAIT0()   asm volatile("cp.async.wait_group 0;" ::: "memory")

// ============================================================
// Kernel 0: weight transposes for ic-pair layout
// ============================================================
__global__ void k_prep(const float* __restrict__ w2, const float* __restrict__ w3) {
    int i = blockIdx.x * blockDim.x + threadIdx.x;
    if (i < 5 * 64 * 128) {
        int k = i >> 13, oc = (i >> 7) & 63, ic = i & 127;
        g_w2T[i] = w2[oc * 640 + ic * 5 + k];
    }
    if (i < 3 * 64 * 64) {
        int k = i >> 12, oc = (i >> 6) & 63, ic = i & 63;
        g_w3T[i] = w3[oc * 192 + ic * 3 + k];
    }
}

// ============================================================
// Kernel 1: conv1 (3->128, k3) + BN + pool(3,2) + relu -> g_h1T[b][pos][ic]
// ============================================================
__global__ void __launch_bounds__(128) k_conv1(
        const float* __restrict__ x,
        const float* __restrict__ w,
        const float* __restrict__ bias,
        const float* __restrict__ bng,
        const float* __restrict__ bnb,
        const float* __restrict__ bnm,
        const float* __restrict__ bnv) {
    const int b  = blockIdx.y;
    const int p0 = blockIdx.x * 64;
    const int oc = threadIdx.x;
    __shared__ float xs[3][132];
    __shared__ float outS[64][128];

    const int t0 = 2 * p0;
    for (int idx = threadIdx.x; idx < 3 * 131; idx += 128) {
        int ch = idx / 131, j = idx % 131;
        int t = t0 + j;
        xs[ch][j] = (t < SIGLEN) ? x[(b * 3 + ch) * SIGLEN + t] : 0.f;
    }
    float wr[9];
#pragma unroll
    for (int j = 0; j < 9; ++j) wr[j] = w[oc * 9 + j];
    float scale = bng[oc] / sqrtf(bnv[oc] + EPS_BN);
    float shift = bnb[oc] + (bias[oc] - bnm[oc]) * scale;
    __syncthreads();

#pragma unroll 4
    for (int pl = 0; pl < 64; ++pl) {
        float c0 = 0.f, c1 = 0.f, c2 = 0.f;
        int base = 2 * pl;
#pragma unroll
        for (int ch = 0; ch < 3; ++ch)
#pragma unroll
            for (int k = 0; k < 3; ++k) {
                float wv = wr[ch * 3 + k];
                c0 = fmaf(wv, xs[ch][base + k], c0);
                c1 = fmaf(wv, xs[ch][base + 1 + k], c1);
                c2 = fmaf(wv, xs[ch][base + 2 + k], c2);
            }
        float y0 = fmaf(c0, scale, shift);
        float y1 = fmaf(c1, scale, shift);
        float y2 = fmaf(c2, scale, shift);
        outS[pl][oc] = fmaxf(fmaxf(fmaxf(y0, y1), y2), 0.f);
    }
    __syncthreads();
    for (int idx = threadIdx.x; idx < 64 * 128; idx += 128) {
        int pl = idx >> 7, col = idx & 127;
        int p = p0 + pl;
        if (p < L1P) g_h1T[(b * L1P + p) * C1 + col] = outS[pl][col];
    }
}

// ============================================================
// Kernel 2: conv2 (128->64, k5) + BN + pool(3,3) + relu   [HOT]
// ic-pair f32x2, cp.async double-buffered. -> g_h2T[b][pos][oc]
// thread = (ocd 0..31, gg 0..7): 2 oc (ocd, ocd+32), 6 conv = 2 pooled.
// tile 16 pooled (48 conv, 52 input span). grid (22, 256).
// ============================================================
__global__ void __launch_bounds__(256) k_conv2(
        const float* __restrict__ bias,
        const float* __restrict__ bng,
        const float* __restrict__ bnb,
        const float* __restrict__ bnm,
        const float* __restrict__ bnv) {
    const int b   = blockIdx.y;
    const int p0  = blockIdx.x * 16;
    const int tid = threadIdx.x;
    const int ocd = tid & 31;
    const int gg  = tid >> 5;
    const int tin0 = 3 * p0;

    __shared__ float xs[2][52][16];
    __shared__ ull   ws[2][2560];       // [k*8+icp][oc]
    __shared__ float outS[64][18];

    ull acc0[6], acc1[6];
#pragma unroll
    for (int m = 0; m < 6; ++m) { acc0[m] = 0ull; acc1[m] = 0ull; }

    // fill chunk c into buffer bi
    auto fill = [&](int c, int bi) {
        const int ic0 = c * 16;
        for (int idx = tid; idx < 52 * 4; idx += 256) {
            int j = idx >> 2, q = idx & 3;
            int t = tin0 + j;
            float* dst = &xs[bi][j][q * 4];
            if (t < L1P) {
                cpa16(dst, &g_h1T[(b * L1P + t) * C1 + ic0 + q * 4]);
            } else {
                dst[0] = 0.f; dst[1] = 0.f; dst[2] = 0.f; dst[3] = 0.f;
            }
        }
        for (int idx = tid; idx < 2560; idx += 256) {
            int oc = idx & 63, r = idx >> 6;      // r = k*8+icp
            int k = r >> 3, icp = r & 7;
            cpa8(&ws[bi][idx], &g_w2T[(k * 64 + oc) * 128 + ic0 + 2 * icp]);
        }
    };

    fill(0, 0); CP_COMMIT();
    for (int c = 0; c < 8; ++c) {
        if (c + 1 < 8) { fill(c + 1, (c + 1) & 1); CP_COMMIT(); CP_WAIT1(); }
        else           { CP_WAIT0(); }
        __syncthreads();
        const int bi = c & 1;
#pragma unroll
        for (int icp = 0; icp < 8; ++icp) {
            ull xd[10];
#pragma unroll
            for (int j = 0; j < 10; ++j)
                xd[j] = *(const ull*)&xs[bi][6 * gg + j][2 * icp];
            ull w0[5], w1[5];
#pragma unroll
            for (int k = 0; k < 5; ++k) {
                w0[k] = ws[bi][(k * 8 + icp) * 64 + ocd];
                w1[k] = ws[bi][(k * 8 + icp) * 64 + ocd + 32];
            }
#pragma unroll
            for (int m = 0; m < 6; ++m)
#pragma unroll
                for (int k = 0; k < 5; ++k) {
                    fma2(acc0[m], w0[k], xd[m + k]);
                    fma2(acc1[m], w1[k], xd[m + k]);
                }
        }
        __syncthreads();
    }

#pragma unroll
    for (int o2 = 0; o2 < 2; ++o2) {
        int oc = ocd + 32 * o2;
        float scale = bng[oc] / sqrtf(bnv[oc] + EPS_BN);
        float shift = bnb[oc] + (bias[oc] - bnm[oc]) * scale;
        float cvals[6];
#pragma unroll
        for (int m = 0; m < 6; ++m) {
            ull a = o2 ? acc1[m] : acc0[m];
            cvals[m] = lo32(a) + hi32(a);
        }
#pragma unroll
        for (int j = 0; j < 2; ++j) {
            float y0 = fmaf(cvals[3 * j],     scale, shift);
            float y1 = fmaf(cvals[3 * j + 1], scale, shift);
            float y2 = fmaf(cvals[3 * j + 2], scale, shift);
            outS[oc][gg * 2 + j] = fmaxf(fmaxf(fmaxf(y0, y1), y2), 0.f);
        }
    }
    __syncthreads();
    for (int idx = tid; idx < 64 * 16; idx += 256) {
        int o = idx & 63, pl = idx >> 6;
        int p = p0 + pl;
        if (p < L2P) g_h2T[(b * L2P + p) * C2 + o] = outS[o][pl];
    }
}

// ============================================================
// Kernel 3: conv3 (64->64, k3) + BN + pool(3,2) + relu -> g_h3T[feat][batch]
// ic-pair f32x2, cp.async double-buffered.
// thread = (ocd 0..31, gg 0..7): 2 oc, 5 conv = 2 pooled (overlapping).
// tile 16 pooled (33 conv, 35 input). grid (11, 256).
// ============================================================
__global__ void __launch_bounds__(256) k_conv3(
        const float* __restrict__ bias,
        const float* __restrict__ bng,
        const float* __restrict__ bnb,
        const float* __restrict__ bnm,
        const float* __restrict__ bnv) {
    const int b   = blockIdx.y;
    const int p0  = blockIdx.x * 16;
    const int tid = threadIdx.x;
    const int ocd = tid & 31;
    const int gg  = tid >> 5;
    const int tin0 = 2 * p0;

    __shared__ float xs[2][36][16];
    __shared__ ull   ws[2][1536];      // [k*8+icp][oc]

    ull acc0[5], acc1[5];
#pragma unroll
    for (int m = 0; m < 5; ++m) { acc0[m] = 0ull; acc1[m] = 0ull; }

    auto fill = [&](int c, int bi) {
        const int ic0 = c * 16;
        for (int idx = tid; idx < 35 * 4; idx += 256) {
            int j = idx >> 2, q = idx & 3;
            int t = tin0 + j;
            float* dst = &xs[bi][j][q * 4];
            if (t < L2P) {
                cpa16(dst, &g_h2T[(b * L2P + t) * C2 + ic0 + q * 4]);
            } else {
                dst[0] = 0.f; dst[1] = 0.f; dst[2] = 0.f; dst[3] = 0.f;
            }
        }
        for (int idx = tid; idx < 1536; idx += 256) {
            int oc = idx & 63, r = idx >> 6;       // r = k*8+icp
            int k = r >> 3, icp = r & 7;
            cpa8(&ws[bi][idx], &g_w3T[(k * 64 + oc) * 64 + ic0 + 2 * icp]);
        }
    };

    fill(0, 0); CP_COMMIT();
    for (int c = 0; c < 4; ++c) {
        if (c + 1 < 4) { fill(c + 1, (c + 1) & 1); CP_COMMIT(); CP_WAIT1(); }
        else           { CP_WAIT0(); }
        __syncthreads();
        const int bi = c & 1;
#pragma unroll
        for (int icp = 0; icp < 8; ++icp) {
            ull xd[7];
#pragma unroll
            for (int j = 0; j < 7; ++j)
                xd[j] = *(const ull*)&xs[bi][4 * gg + j][2 * icp];
            ull w0[3], w1[3];
#pragma unroll
            for (int k = 0; k < 3; ++k) {
                w0[k] = ws[bi][(k * 8 + icp) * 64 + ocd];
                w1[k] = ws[bi][(k * 8 + icp) * 64 + ocd + 32];
            }
#pragma unroll
            for (int m = 0; m < 5; ++m)
#pragma unroll
                for (int k = 0; k < 3; ++k) {
                    fma2(acc0[m], w0[k], xd[m + k]);
                    fma2(acc1[m], w1[k], xd[m + k]);
                }
        }
        __syncthreads();
    }

#pragma unroll
    for (int o2 = 0; o2 < 2; ++o2) {
        int oc = ocd + 32 * o2;
        float scale = bng[oc] / sqrtf(bnv[oc] + EPS_BN);
        float shift = bnb[oc] + (bias[oc] - bnm[oc]) * scale;
        float cvals[5];
#pragma unroll
        for (int m = 0; m < 5; ++m) {
            ull a = o2 ? acc1[m] : acc0[m];
            cvals[m] = lo32(a) + hi32(a);
        }
#pragma unroll
        for (int j = 0; j < 2; ++j) {
            int p = p0 + 2 * gg + j;
            if (p >= L3P) continue;
            float y0 = fmaf(cvals[2 * j],     scale, shift);
            float y1 = fmaf(cvals[2 * j + 1], scale, shift);
            float y2 = fmaf(cvals[2 * j + 2], scale, shift);
            float y = fmaxf(fmaxf(fmaxf(y0, y1), y2), 0.f);
            g_h3T[(oc * L3P + p) * BATCH + b] = y;
        }
    }
}

// ============================================================
// Kernel 4a: fc1 split-K. 192 blocks x 56-wide K chunks.
// ============================================================
__global__ void __launch_bounds__(256) k_fcA(const float* __restrict__ fc1w) {
    const int chunk = blockIdx.x;
    const int r = threadIdx.x;
    __shared__ float2 ws2[56][24];

    for (int idx = r; idx < 56 * 24; idx += 256) {
        int pr = idx % 24, k = idx / 24;
        int kg = chunk * 56 + k;
        ws2[k][pr] = make_float2(fc1w[pr * FCIN + kg],
                                 fc1w[(pr + 24) * FCIN + kg]);
    }
    __syncthreads();

    ull acc[24];
#pragma unroll
    for (int p = 0; p < 24; ++p) acc[p] = 0ull;

#pragma unroll 4
    for (int k = 0; k < 56; ++k) {
        float xv = g_h3T[(chunk * 56 + k) * BATCH + r];
        ull xd = dup2(xv);
#pragma unroll
        for (int p = 0; p < 24; ++p)
            fma2(acc[p], *(const ull*)&ws2[k][p], xd);
    }
    float* outp = &g_part[(chunk * BATCH + r) * 48];
#pragma unroll
    for (int p = 0; p < 24; ++p) {
        outp[p]      = lo32(acc[p]);
        outp[p + 24] = hi32(acc[p]);
    }
}

// ============================================================
// Kernel 4b: reduce + fc2/fc3/fc4 + tanh
// ============================================================
__global__ void k_fcB(const float* __restrict__ fc1b,
                      const float* __restrict__ fc2w, const float* __restrict__ fc2b,
                      const float* __restrict__ fc3w, const float* __restrict__ fc3b,
                      const float* __restrict__ fc4w, const float* __restrict__ fc4b) {
    const int r = blockIdx.x;
    const int t = threadIdx.x;
    __shared__ float s1[48], s2[32], s3[16];

    if (t < 48) {
        float a = 0.f;
#pragma unroll 8
        for (int c = 0; c < 192; ++c)
            a += g_part[(c * BATCH + r) * 48 + t];
        s1[t] = fmaxf(a + fc1b[t], 0.f);
    }
    __syncthreads();
    if (t < 32) {
        float a2 = 0.f;
#pragma unroll
        for (int k = 0; k < 48; ++k) a2 = fmaf(s1[k], fc2w[t * 48 + k], a2);
        s2[t] = fmaxf(a2 + fc2b[t], 0.f);
    }
    __syncthreads();
    if (t < 16) {
        float a3 = 0.f;
#pragma unroll
        for (int k = 0; k < 32; ++k) a3 = fmaf(s2[k], fc3w[t * 32 + k], a3);
        s3[t] = fmaxf(a3 + fc3b[t], 0.f);
    }
    __syncthreads();
    if (t < 5) {
        float a4 = 0.f;
#pragma unroll
        for (int k = 0; k < 16; ++k) a4 = fmaf(s3[k], fc4w[t * 16 + k], a4);
        g_theta[r * 5 + t] = tanhf(a4 + fc4b[t]);
    }
}

// ============================================================
// Kernel 5: CPAB integrate + resample
// ============================================================
__global__ void k_warp(const float* __restrict__ x,
                       const float* __restrict__ basis,
                       float* __restrict__ out) {
    const int b   = blockIdx.x;
    const int tid = threadIdx.x;
    __shared__ float sa[6], sb[6];
    if (tid < 12) {
        float a = 0.f;
#pragma unroll
        for (int k = 0; k < 5; ++k)
            a = fmaf(g_theta[b * 5 + k], basis[tid * 5 + k], a);
        if (tid & 1) sb[tid >> 1] = a; else sa[tid >> 1] = a;
    }
    __syncthreads();
    float la[6], lb[6];
#pragma unroll
    for (int c = 0; c < 6; ++c) { la[c] = sa[c]; lb[c] = sb[c]; }
    const float INF = __int_as_float(0x7f800000);

    for (int r = 0; r < 8; ++r) {
        int i = tid + r * 256;
        float xv = (float)i / 2047.0f;
        float t = 1.0f;
#pragma unroll 1
        for (int it = 0; it < 7; ++it) {
            int c = (int)floorf(xv * 6.0f);
            c = c < 0 ? 0 : (c > 5 ? 5 : c);
            float a  = la[c];
            float bc = lb[c];
            float v  = fmaf(a, xv, bc);
            float xb = (v >= 0.f) ? (float)(c + 1) / 6.0f : (float)c / 6.0f;
            bool  big = fabsf(a) > 1e-8f;
            float a_s = big ? a : 1.0f;
            float boa = bc / a_s;
            float z   = xv + boa;
            float zb  = xb + boa;
            float zden  = (fabsf(z) > 1e-12f) ? z : 1e-12f;
            float ratio = zb / zden;
            float t_exp = logf(fmaxf(ratio, 1e-12f)) / a_s;
            float v_s   = (fabsf(v) > 1e-12f) ? v : 1.0f;
            float t_lin = (xb - xv) / v_s;
            float thit  = big ? t_exp : t_lin;
            bool valid = (fabsf(v) > 1e-12f) && (thit > 0.f) &&
                         ((big ? ratio : 1.0f) > 0.f);
            thit = valid ? thit : INF;
            float tau = fminf(t, thit);
            float x_new = big ? (z * expf(a * tau) - (z - xv))
                              : fmaf(bc, tau, xv);
            bool hit = (thit <= t);
            float nudge = (v >= 0.f) ? 1e-6f : -1e-6f;
            xv = hit ? (xb + nudge) : x_new;
            xv = fminf(fmaxf(xv, 0.f), 1.f);
            t = fmaxf(t - tau, 0.f);
        }
        float p = fminf(fmaxf(xv, 0.f), 1.f) * 2047.0f;
        int x0 = (int)floorf(p);
        x0 = x0 < 0 ? 0 : (x0 > 2046 ? 2046 : x0);
        float wgt = p - (float)x0;
#pragma unroll
        for (int ch = 0; ch < 3; ++ch) {
            float d0 = x[(b * 3 + ch) * SIGLEN + x0];
            float d1 = x[(b * 3 + ch) * SIGLEN + x0 + 1];
            out[(b * 3 + ch) * SIGLEN + i] = d0 * (1.0f - wgt) + d1 * wgt;
        }
    }
}

// ============================================================
extern "C" void kernel_launch(void* const* d_in, const int* in_sizes, int n_in,
                              void* d_out, int out_size) {
    const float* x     = (const float*)d_in[0];
    const float* c1w   = (const float*)d_in[1];
    const float* c1b   = (const float*)d_in[2];
    const float* bn1g  = (const float*)d_in[3];
    const float* bn1b  = (const float*)d_in[4];
    const float* bn1m  = (const float*)d_in[5];
    const float* bn1v  = (const float*)d_in[6];
    const float* c2w   = (const float*)d_in[7];
    const float* c2b   = (const float*)d_in[8];
    const float* bn2g  = (const float*)d_in[9];
    const float* bn2b  = (const float*)d_in[10];
    const float* bn2m  = (const float*)d_in[11];
    const float* bn2v  = (const float*)d_in[12];
    const float* c3w   = (const float*)d_in[13];
    const float* c3b   = (const float*)d_in[14];
    const float* bn3g  = (const float*)d_in[15];
    const float* bn3b  = (const float*)d_in[16];
    const float* bn3m  = (const float*)d_in[17];
    const float* bn3v  = (const float*)d_in[18];
    const float* fc1w  = (const float*)d_in[19];
    const float* fc1b  = (const float*)d_in[20];
    const float* fc2w  = (const float*)d_in[21];
    const float* fc2b  = (const float*)d_in[22];
    const float* fc3w  = (const float*)d_in[23];
    const float* fc3b  = (const float*)d_in[24];
    const float* fc4w  = (const float*)d_in[25];
    const float* fc4b  = (const float*)d_in[26];
    const float* basis = (const float*)d_in[27];
    float* out = (float*)d_out;

    k_prep<<<160, 256>>>(c2w, c3w);
    dim3 g1(16, BATCH);  k_conv1<<<g1, 128>>>(x, c1w, c1b, bn1g, bn1b, bn1m, bn1v);
    dim3 g2(22, BATCH);  k_conv2<<<g2, 256>>>(c2b, bn2g, bn2b, bn2m, bn2v);
    dim3 g3(11, BATCH);  k_conv3<<<g3, 256>>>(c3b, bn3g, bn3b, bn3m, bn3v);
    k_fcA<<<192, 256>>>(fc1w);
    k_fcB<<<BATCH, 64>>>(fc1b, fc2w, fc2b, fc3w, fc3b, fc4w, fc4b);
    k_warp<<<BATCH, 256>>>(x, basis, out);
}

// round 6
// speedup vs baseline: 1.5213x; 1.2449x over previous
#include <cuda_runtime.h>
#include <math.h>
#include <stdint.h>

#define BATCH 256
#define SIGLEN 2048
#define L1P 1022
#define L2P 339
#define L3P 168
#define C1 128
#define C2 64
#define C3 64
#define FCIN 10752
#define EPS_BN 1e-5f

typedef unsigned long long ull;

// ---- scratch ----
__device__ float g_h1T[BATCH * L1P * C1];   // [b][pos][ic]
__device__ float g_h2T[BATCH * L2P * C2];   // [b][pos][oc]
__device__ float g_h3T[FCIN * BATCH];       // [feature][batch]
__device__ float g_w2T[5 * 64 * 128];       // [k][oc][ic]
__device__ float g_w3T[3 * 64 * 64];        // [k][oc][ic]
__device__ float g_part[256 * BATCH * 48];
__device__ float g_theta[BATCH * 5];

__device__ __forceinline__ void fma2(ull& d, ull a, ull b) {
    asm("fma.rn.f32x2 %0, %1, %2, %0;" : "+l"(d) : "l"(a), "l"(b));
}
__device__ __forceinline__ ull dup2(float v) {
    ull r; asm("mov.b64 %0, {%1, %1};" : "=l"(r) : "f"(v)); return r;
}
__device__ __forceinline__ float lo32(ull v) { return __uint_as_float((unsigned)v); }
__device__ __forceinline__ float hi32(ull v) { return __uint_as_float((unsigned)(v >> 32)); }

__device__ __forceinline__ void cpa16(void* dst, const void* src) {
    unsigned d = (unsigned)__cvta_generic_to_shared(dst);
    asm volatile("cp.async.cg.shared.global [%0], [%1], 16;" :: "r"(d), "l"(src));
}
__device__ __forceinline__ void cpa8(void* dst, const void* src) {
    unsigned d = (unsigned)__cvta_generic_to_shared(dst);
    asm volatile("cp.async.ca.shared.global [%0], [%1], 8;" :: "r"(d), "l"(src));
}
#define CP_COMMIT()  asm volatile("cp.async.commit_group;" ::: "memory")
#define CP_WAIT1()   asm volatile("cp.async.wait_group 1;" ::: "memory")
#define CP_WAIT0()   asm volatile("cp.async.wait_group 0;" ::: "memory")

// ============================================================
// Kernel 0: weight transposes
// ============================================================
__global__ void k_prep(const float* __restrict__ w2, const float* __restrict__ w3) {
    int i = blockIdx.x * blockDim.x + threadIdx.x;
    if (i < 5 * 64 * 128) {
        int k = i >> 13, oc = (i >> 7) & 63, ic = i & 127;
        g_w2T[i] = w2[oc * 640 + ic * 5 + k];
    }
    if (i < 3 * 64 * 64) {
        int k = i >> 12, oc = (i >> 6) & 63, ic = i & 63;
        g_w3T[i] = w3[oc * 192 + ic * 3 + k];
    }
}

// ============================================================
// Kernel 1: conv1 (3->128, k3) + BN + pool(3,2) + relu -> g_h1T[b][pos][ic]
// ============================================================
__global__ void __launch_bounds__(128) k_conv1(
        const float* __restrict__ x,
        const float* __restrict__ w,
        const float* __restrict__ bias,
        const float* __restrict__ bng,
        const float* __restrict__ bnb,
        const float* __restrict__ bnm,
        const float* __restrict__ bnv) {
    const int b  = blockIdx.y;
    const int p0 = blockIdx.x * 64;
    const int oc = threadIdx.x;
    __shared__ float xs[3][132];
    __shared__ float outS[64][128];

    const int t0 = 2 * p0;
    for (int idx = threadIdx.x; idx < 3 * 131; idx += 128) {
        int ch = idx / 131, j = idx % 131;
        int t = t0 + j;
        xs[ch][j] = (t < SIGLEN) ? x[(b * 3 + ch) * SIGLEN + t] : 0.f;
    }
    float wr[9];
#pragma unroll
    for (int j = 0; j < 9; ++j) wr[j] = w[oc * 9 + j];
    float scale = bng[oc] / sqrtf(bnv[oc] + EPS_BN);
    float shift = bnb[oc] + (bias[oc] - bnm[oc]) * scale;
    __syncthreads();

#pragma unroll 4
    for (int pl = 0; pl < 64; ++pl) {
        float c0 = 0.f, c1 = 0.f, c2 = 0.f;
        int base = 2 * pl;
#pragma unroll
        for (int ch = 0; ch < 3; ++ch)
#pragma unroll
            for (int k = 0; k < 3; ++k) {
                float wv = wr[ch * 3 + k];
                c0 = fmaf(wv, xs[ch][base + k], c0);
                c1 = fmaf(wv, xs[ch][base + 1 + k], c1);
                c2 = fmaf(wv, xs[ch][base + 2 + k], c2);
            }
        float y0 = fmaf(c0, scale, shift);
        float y1 = fmaf(c1, scale, shift);
        float y2 = fmaf(c2, scale, shift);
        outS[pl][oc] = fmaxf(fmaxf(fmaxf(y0, y1), y2), 0.f);
    }
    __syncthreads();
    for (int idx = threadIdx.x; idx < 64 * 128; idx += 128) {
        int pl = idx >> 7, col = idx & 127;
        int p = p0 + pl;
        if (p < L1P) g_h1T[(b * L1P + p) * C1 + col] = outS[pl][col];
    }
}

// ============================================================
// Kernel 2: conv2 (128->64, k5) + BN + pool(3,3) + relu  [HOT]
// ic-pair f32x2, register-blocked: 12 conv pos x 2 oc-pairs (4 oc)
// per thread -> 120 fma2 / 208 LDS-B per icp (fma-bound).
// Tile: 96 conv = 32 pooled. grid (11, 256), block 256 (32 ocd x 8 gg).
// Direct warp-coalesced pooled output (12 conv = 4 pooled per thread).
// ============================================================
#define CV2_SMEM (2 * 6400 + 2 * 20480)   // xs(2) + ws(2) = 53760 B

__global__ void __launch_bounds__(256, 2) k_conv2(
        const float* __restrict__ bias,
        const float* __restrict__ bng,
        const float* __restrict__ bnb,
        const float* __restrict__ bnm,
        const float* __restrict__ bnv) {
    extern __shared__ char smem[];
    float (*xs0)[16] = (float(*)[16])(smem);
    float (*xs1)[16] = (float(*)[16])(smem + 6400);
    ull* ws0 = (ull*)(smem + 12800);
    ull* ws1 = (ull*)(smem + 33280);

    const int b   = blockIdx.y;
    const int ct0 = blockIdx.x * 96;      // first conv position of tile
    const int tid = threadIdx.x;
    const int ocd = tid & 31;
    const int gg  = tid >> 5;

    const float* h1b = &g_h1T[(size_t)b * L1P * C1];

    ull acc0[12], acc1[12];
#pragma unroll
    for (int m = 0; m < 12; ++m) { acc0[m] = 0ull; acc1[m] = 0ull; }

    auto fill = [&](int c, int bi) {
        float (*xsb)[16] = bi ? xs1 : xs0;
        ull* wsb = bi ? ws1 : ws0;
        const int ic0 = c * 16;
        for (int idx = tid; idx < 400; idx += 256) {
            int j = idx >> 2, q = idx & 3;
            int t = ct0 + j;
            float* dst = &xsb[j][q * 4];
            if (t < L1P) cpa16(dst, &h1b[t * C1 + ic0 + q * 4]);
            else { dst[0] = 0.f; dst[1] = 0.f; dst[2] = 0.f; dst[3] = 0.f; }
        }
        for (int idx = tid; idx < 2560; idx += 256) {
            int oc = idx & 63, r = idx >> 6;        // r = k*8+icp
            cpa8(&wsb[idx], &g_w2T[((r >> 3) * 64 + oc) * 128 + ic0 + 2 * (r & 7)]);
        }
    };

    fill(0, 0); CP_COMMIT();
    for (int c = 0; c < 8; ++c) {
        if (c + 1 < 8) { fill(c + 1, (c + 1) & 1); CP_COMMIT(); CP_WAIT1(); }
        else           { CP_WAIT0(); }
        __syncthreads();
        float (*xsb)[16] = (c & 1) ? xs1 : xs0;
        ull* wsb = (c & 1) ? ws1 : ws0;
#pragma unroll 1
        for (int icp = 0; icp < 8; ++icp) {
            ull xd[16];
#pragma unroll
            for (int j = 0; j < 16; ++j)
                xd[j] = *(const ull*)&xsb[12 * gg + j][2 * icp];
            ull w0[5], w1[5];
#pragma unroll
            for (int k = 0; k < 5; ++k) {
                w0[k] = wsb[(k * 8 + icp) * 64 + ocd];
                w1[k] = wsb[(k * 8 + icp) * 64 + ocd + 32];
            }
#pragma unroll
            for (int m = 0; m < 12; ++m)
#pragma unroll
                for (int k = 0; k < 5; ++k) {
                    fma2(acc0[m], w0[k], xd[m + k]);
                    fma2(acc1[m], w1[k], xd[m + k]);
                }
        }
        __syncthreads();
    }

    // epilogue: 12 conv = 4 pooled per thread, direct coalesced write
#pragma unroll
    for (int o2 = 0; o2 < 2; ++o2) {
        int oc = ocd + 32 * o2;
        float scale = bng[oc] / sqrtf(bnv[oc] + EPS_BN);
        float shift = bnb[oc] + (bias[oc] - bnm[oc]) * scale;
#pragma unroll
        for (int j = 0; j < 4; ++j) {
            int p = blockIdx.x * 32 + 4 * gg + j;
            if (p >= L2P) continue;
            ull a0 = o2 ? acc1[3 * j] : acc0[3 * j];
            ull a1 = o2 ? acc1[3 * j + 1] : acc0[3 * j + 1];
            ull a2 = o2 ? acc1[3 * j + 2] : acc0[3 * j + 2];
            float y0 = fmaf(lo32(a0) + hi32(a0), scale, shift);
            float y1 = fmaf(lo32(a1) + hi32(a1), scale, shift);
            float y2 = fmaf(lo32(a2) + hi32(a2), scale, shift);
            g_h2T[(b * L2P + p) * C2 + oc] = fmaxf(fmaxf(fmaxf(y0, y1), y2), 0.f);
        }
    }
}

// ============================================================
// Kernel 3: conv3 (64->64, k3) + BN + pool(3,2) + relu -> g_h3T[feat][b]
// 16 ocd lanes x 16 gg groups; 4 oc x 7 conv (3 pooled) per thread.
// 84 fma2 / 168 LDS-B per icp. Tile 96 conv = 48 pooled. grid (4, 256).
// xs rows padded to 20 floats for conflict-free dual-broadcast.
// ============================================================
__global__ void __launch_bounds__(256, 2) k_conv3(
        const float* __restrict__ bias,
        const float* __restrict__ bng,
        const float* __restrict__ bnb,
        const float* __restrict__ bnm,
        const float* __restrict__ bnv) {
    __shared__ float xs[2][99][20];
    __shared__ ull   ws[2][1536];     // [k*8+icp][oc]

    const int b   = blockIdx.y;
    const int ct0 = blockIdx.x * 96;
    const int tid = threadIdx.x;
    const int ocd = tid & 15;
    const int gg  = tid >> 4;

    ull acc[4][7];
#pragma unroll
    for (int q = 0; q < 4; ++q)
#pragma unroll
        for (int m = 0; m < 7; ++m) acc[q][m] = 0ull;

    auto fill = [&](int c, int bi) {
        const int ic0 = c * 16;
        for (int idx = tid; idx < 99 * 4; idx += 256) {
            int j = idx >> 2, q = idx & 3;
            int t = ct0 + j;
            float* dst = &xs[bi][j][q * 4];
            if (t < L2P) cpa16(dst, &g_h2T[(b * L2P + t) * C2 + ic0 + q * 4]);
            else { dst[0] = 0.f; dst[1] = 0.f; dst[2] = 0.f; dst[3] = 0.f; }
        }
        for (int idx = tid; idx < 1536; idx += 256) {
            int oc = idx & 63, r = idx >> 6;     // r = k*8+icp
            cpa8(&ws[bi][idx], &g_w3T[((r >> 3) * 64 + oc) * 64 + ic0 + 2 * (r & 7)]);
        }
    };

    fill(0, 0); CP_COMMIT();
    for (int c = 0; c < 4; ++c) {
        if (c + 1 < 4) { fill(c + 1, (c + 1) & 1); CP_COMMIT(); CP_WAIT1(); }
        else           { CP_WAIT0(); }
        __syncthreads();
        const int bi = c & 1;
#pragma unroll 1
        for (int icp = 0; icp < 8; ++icp) {
            ull xd[9];
#pragma unroll
            for (int j = 0; j < 9; ++j)
                xd[j] = *(const ull*)&xs[bi][6 * gg + j][2 * icp];
            ull wv[4][3];
#pragma unroll
            for (int k = 0; k < 3; ++k) {
#pragma unroll
                for (int q = 0; q < 4; ++q)
                    wv[q][k] = ws[bi][(k * 8 + icp) * 64 + ocd + 16 * q];
            }
#pragma unroll
            for (int m = 0; m < 7; ++m)
#pragma unroll
                for (int k = 0; k < 3; ++k)
#pragma unroll
                    for (int q = 0; q < 4; ++q)
                        fma2(acc[q][m], wv[q][k], xd[m + k]);
        }
        __syncthreads();
    }

#pragma unroll
    for (int q = 0; q < 4; ++q) {
        int oc = ocd + 16 * q;
        float scale = bng[oc] / sqrtf(bnv[oc] + EPS_BN);
        float shift = bnb[oc] + (bias[oc] - bnm[oc]) * scale;
#pragma unroll
        for (int j = 0; j < 3; ++j) {
            int p = blockIdx.x * 48 + 3 * gg + j;
            if (p >= L3P) continue;
            ull a0 = acc[q][2 * j], a1 = acc[q][2 * j + 1], a2 = acc[q][2 * j + 2];
            float y0 = fmaf(lo32(a0) + hi32(a0), scale, shift);
            float y1 = fmaf(lo32(a1) + hi32(a1), scale, shift);
            float y2 = fmaf(lo32(a2) + hi32(a2), scale, shift);
            float y = fmaxf(fmaxf(fmaxf(y0, y1), y2), 0.f);
            g_h3T[(oc * L3P + p) * BATCH + b] = y;
        }
    }
}

// ============================================================
// Kernel 4a: fc1 split-K. 256 blocks x 42-wide K chunks.
// Coalesced weight staging (k fastest); output pairs (2p, 2p+1).
// ============================================================
__global__ void __launch_bounds__(256) k_fcA(const float* __restrict__ fc1w) {
    const int chunk = blockIdx.x;
    const int r = threadIdx.x;
    __shared__ float wsS[42][48];

    for (int idx = r; idx < 42 * 48; idx += 256) {
        int o = idx / 42, k = idx % 42;
        wsS[k][o] = fc1w[o * FCIN + chunk * 42 + k];
    }
    __syncthreads();

    ull acc[24];
#pragma unroll
    for (int p = 0; p < 24; ++p) acc[p] = 0ull;

#pragma unroll 2
    for (int k = 0; k < 42; ++k) {
        float xv = g_h3T[(chunk * 42 + k) * BATCH + r];
        ull xd = dup2(xv);
#pragma unroll
        for (int p = 0; p < 24; ++p)
            fma2(acc[p], *(const ull*)&wsS[k][2 * p], xd);
    }
    float* outp = &g_part[(chunk * BATCH + r) * 48];
#pragma unroll
    for (int p = 0; p < 24; ++p) {
        outp[2 * p]     = lo32(acc[p]);
        outp[2 * p + 1] = hi32(acc[p]);
    }
}

// ============================================================
// Kernel 4b: reduce + fc2/fc3/fc4 + tanh
// ============================================================
__global__ void k_fcB(const float* __restrict__ fc1b,
                      const float* __restrict__ fc2w, const float* __restrict__ fc2b,
                      const float* __restrict__ fc3w, const float* __restrict__ fc3b,
                      const float* __restrict__ fc4w, const float* __restrict__ fc4b) {
    const int r = blockIdx.x;
    const int t = threadIdx.x;
    __shared__ float s1[48], s2[32], s3[16];

    if (t < 48) {
        float a = 0.f;
#pragma unroll 8
        for (int c = 0; c < 256; ++c)
            a += g_part[(c * BATCH + r) * 48 + t];
        s1[t] = fmaxf(a + fc1b[t], 0.f);
    }
    __syncthreads();
    if (t < 32) {
        float a2 = 0.f;
#pragma unroll
        for (int k = 0; k < 48; ++k) a2 = fmaf(s1[k], fc2w[t * 48 + k], a2);
        s2[t] = fmaxf(a2 + fc2b[t], 0.f);
    }
    __syncthreads();
    if (t < 16) {
        float a3 = 0.f;
#pragma unroll
        for (int k = 0; k < 32; ++k) a3 = fmaf(s2[k], fc3w[t * 32 + k], a3);
        s3[t] = fmaxf(a3 + fc3b[t], 0.f);
    }
    __syncthreads();
    if (t < 5) {
        float a4 = 0.f;
#pragma unroll
        for (int k = 0; k < 16; ++k) a4 = fmaf(s3[k], fc4w[t * 16 + k], a4);
        g_theta[r * 5 + t] = tanhf(a4 + fc4b[t]);
    }
}

// ============================================================
// Kernel 5: CPAB integrate + resample
// ============================================================
__global__ void k_warp(const float* __restrict__ x,
                       const float* __restrict__ basis,
                       float* __restrict__ out) {
    const int b   = blockIdx.x;
    const int tid = threadIdx.x;
    __shared__ float sa[6], sb[6];
    if (tid < 12) {
        float a = 0.f;
#pragma unroll
        for (int k = 0; k < 5; ++k)
            a = fmaf(g_theta[b * 5 + k], basis[tid * 5 + k], a);
        if (tid & 1) sb[tid >> 1] = a; else sa[tid >> 1] = a;
    }
    __syncthreads();
    float la[6], lb[6];
#pragma unroll
    for (int c = 0; c < 6; ++c) { la[c] = sa[c]; lb[c] = sb[c]; }
    const float INF = __int_as_float(0x7f800000);

    for (int r = 0; r < 8; ++r) {
        int i = tid + r * 256;
        float xv = (float)i / 2047.0f;
        float t = 1.0f;
#pragma unroll 1
        for (int it = 0; it < 7; ++it) {
            int c = (int)floorf(xv * 6.0f);
            c = c < 0 ? 0 : (c > 5 ? 5 : c);
            float a  = la[c];
            float bc = lb[c];
            float v  = fmaf(a, xv, bc);
            float xb = (v >= 0.f) ? (float)(c + 1) / 6.0f : (float)c / 6.0f;
            bool  big = fabsf(a) > 1e-8f;
            float a_s = big ? a : 1.0f;
            float boa = bc / a_s;
            float z   = xv + boa;
            float zb  = xb + boa;
            float zden  = (fabsf(z) > 1e-12f) ? z : 1e-12f;
            float ratio = zb / zden;
            float t_exp = logf(fmaxf(ratio, 1e-12f)) / a_s;
            float v_s   = (fabsf(v) > 1e-12f) ? v : 1.0f;
            float t_lin = (xb - xv) / v_s;
            float thit  = big ? t_exp : t_lin;
            bool valid = (fabsf(v) > 1e-12f) && (thit > 0.f) &&
                         ((big ? ratio : 1.0f) > 0.f);
            thit = valid ? thit : INF;
            float tau = fminf(t, thit);
            float x_new = big ? (z * expf(a * tau) - (z - xv))
                              : fmaf(bc, tau, xv);
            bool hit = (thit <= t);
            float nudge = (v >= 0.f) ? 1e-6f : -1e-6f;
            xv = hit ? (xb + nudge) : x_new;
            xv = fminf(fmaxf(xv, 0.f), 1.f);
            t = fmaxf(t - tau, 0.f);
        }
        float p = fminf(fmaxf(xv, 0.f), 1.f) * 2047.0f;
        int x0 = (int)floorf(p);
        x0 = x0 < 0 ? 0 : (x0 > 2046 ? 2046 : x0);
        float wgt = p - (float)x0;
#pragma unroll
        for (int ch = 0; ch < 3; ++ch) {
            float d0 = x[(b * 3 + ch) * SIGLEN + x0];
            float d1 = x[(b * 3 + ch) * SIGLEN + x0 + 1];
            out[(b * 3 + ch) * SIGLEN + i] = d0 * (1.0f - wgt) + d1 * wgt;
        }
    }
}

// ============================================================
extern "C" void kernel_launch(void* const* d_in, const int* in_sizes, int n_in,
                              void* d_out, int out_size) {
    const float* x     = (const float*)d_in[0];
    const float* c1w   = (const float*)d_in[1];
    const float* c1b   = (const float*)d_in[2];
    const float* bn1g  = (const float*)d_in[3];
    const float* bn1b  = (const float*)d_in[4];
    const float* bn1m  = (const float*)d_in[5];
    const float* bn1v  = (const float*)d_in[6];
    const float* c2w   = (const float*)d_in[7];
    const float* c2b   = (const float*)d_in[8];
    const float* bn2g  = (const float*)d_in[9];
    const float* bn2b  = (const float*)d_in[10];
    const float* bn2m  = (const float*)d_in[11];
    const float* bn2v  = (const float*)d_in[12];
    const float* c3w   = (const float*)d_in[13];
    const float* c3b   = (const float*)d_in[14];
    const float* bn3g  = (const float*)d_in[15];
    const float* bn3b  = (const float*)d_in[16];
    const float* bn3m  = (const float*)d_in[17];
    const float* bn3v  = (const float*)d_in[18];
    const float* fc1w  = (const float*)d_in[19];
    const float* fc1b  = (const float*)d_in[20];
    const float* fc2w  = (const float*)d_in[21];
    const float* fc2b  = (const float*)d_in[22];
    const float* fc3w  = (const float*)d_in[23];
    const float* fc3b  = (const float*)d_in[24];
    const float* fc4w  = (const float*)d_in[25];
    const float* fc4b  = (const float*)d_in[26];
    const float* basis = (const float*)d_in[27];
    float* out = (float*)d_out;

    static int attr_done = 0;
    if (!attr_done) {
        cudaFuncSetAttribute(k_conv2,
                             cudaFuncAttributeMaxDynamicSharedMemorySize, CV2_SMEM);
        attr_done = 1;
    }

    k_prep<<<160, 256>>>(c2w, c3w);
    dim3 g1(16, BATCH);  k_conv1<<<g1, 128>>>(x, c1w, c1b, bn1g, bn1b, bn1m, bn1v);
    dim3 g2(11, BATCH);  k_conv2<<<g2, 256, CV2_SMEM>>>(c2b, bn2g, bn2b, bn2m, bn2v);
    dim3 g3(4,  BATCH);  k_conv3<<<g3, 256>>>(c3b, bn3g, bn3b, bn3m, bn3v);
    k_fcA<<<256, 256>>>(fc1w);
    k_fcB<<<BATCH, 64>>>(fc1b, fc2w, fc2b, fc3w, fc3b, fc4w, fc4b);
    k_warp<<<BATCH, 256>>>(x, basis, out);
}